// round 4
// baseline (speedup 1.0000x reference)
#include <cuda_runtime.h>

#define BDIM 64
#define WPB 2            // warps (MLPs) per block
#define RS 154           // xsT row stride (floats)
#define RSC 54           // rec row stride (floats); 54%32=22 -> conflict-free spans
#define CHUNK 50
#define NCHUNK 3
#define NROWS 43         // rec rows: dh1m[10] h1[10] dg[10] h2[10] d[3]
#define RECW (NROWS * RSC)
#define PSTRIDE 272      // per-MLP param smem floats

typedef unsigned long long u64;

__constant__ float c_lr[6] = {0.001f, 0.01f, 0.05f, 0.1f, 0.5f, 1.0f};
__device__ float g_sumsq = 0.f;   // zeroed by k_zero at END of each call

__device__ __forceinline__ float clip1e4(float v) {
    return fminf(fmaxf(v, -10000.f), 10000.f);
}
__device__ __forceinline__ u64 pk(float lo, float hi) {
    u64 r; asm("mov.b64 %0, {%1,%2};" : "=l"(r) : "f"(lo), "f"(hi)); return r;
}
__device__ __forceinline__ void upk(u64 v, float& lo, float& hi) {
    asm("mov.b64 {%0,%1}, %2;" : "=f"(lo), "=f"(hi) : "l"(v));
}
__device__ __forceinline__ u64 ffma2(u64 a, u64 b, u64 c) {
    u64 d; asm("fma.rn.f32x2 %0, %1, %2, %3;" : "=l"(d) : "l"(a), "l"(b), "l"(c));
    return d;
}
__device__ __forceinline__ u64 fmul2(u64 a, u64 b) {
    u64 d; asm("mul.rn.f32x2 %0, %1, %2;" : "=l"(d) : "l"(a), "l"(b)); return d;
}

__global__ void k_zero() { g_sumsq = 0.f; }

__global__ void __launch_bounds__(BDIM, 8) k_main(
    const float* __restrict__ W1, const float* __restrict__ b1,
    const float* __restrict__ W2, const float* __restrict__ b2,
    const float* __restrict__ W3, const float* __restrict__ b3,
    const float* __restrict__ G1, const float* __restrict__ G2,
    const float* __restrict__ G3, const float* __restrict__ G4,
    const float* __restrict__ G5, const float* __restrict__ G6,
    const float* __restrict__ dx, const float* __restrict__ fv,
    const int* __restrict__ dy, const int* __restrict__ ss,
    float* __restrict__ out)
{
    // xsT rows 0..3 = x features (transposed), row 4 = ones
    __shared__ __align__(16) float xsT[5 * RS];
    __shared__ int   ys[152];
    __shared__ __align__(16) float ps[WPB * PSTRIDE];
    __shared__ __align__(16) float rec[WPB * RECW];

    const int tid  = threadIdx.x;
    const int lane = tid & 31;
    const int warp = tid >> 5;
    const int b    = blockIdx.x * WPB + warp;

    for (int i = tid; i < 150; i += BDIM) {
        const float4 xv = ((const float4*)dx)[i];
        xsT[0 * RS + i] = xv.x;
        xsT[1 * RS + i] = xv.y;
        xsT[2 * RS + i] = xv.z;
        xsT[3 * RS + i] = xv.w;
        xsT[4 * RS + i] = 1.f;
        ys[i] = dy[i];
    }

    float* P    = ps  + warp * PSTRIDE;
    float* recW = rec + warp * RECW;
    // P layout: 0:W1[10x4] 40:b1[10] 52:W2 rows stride 12 (10 rows)
    // 172:b2[10] 184:W3 rows stride 12 (3 rows) 220:b3[3] 224:W3^T stride 4

    const float lr = c_lr[ss[b]];
    float* wout = out + (size_t)b * 388;

    // ---- SGD update into SMEM, clipped params to output ----
    for (int k = lane; k < 40; k += 32) {
        float p = fmaf(-lr, G1[b * 40 + k], W1[b * 40 + k]);
        P[k] = p; wout[k] = clip1e4(p);
    }
    for (int k = lane; k < 10; k += 32) {
        float p = fmaf(-lr, G2[b * 10 + k], b1[b * 10 + k]);
        P[40 + k] = p; wout[40 + k] = clip1e4(p);
    }
    for (int k = lane; k < 100; k += 32) {
        float p = fmaf(-lr, G3[b * 100 + k], W2[b * 100 + k]);
        int r = k / 10, c = k - r * 10;
        P[52 + 12 * r + c] = p; wout[50 + k] = clip1e4(p);
    }
    for (int k = lane; k < 10; k += 32) {
        float p = fmaf(-lr, G4[b * 10 + k], b2[b * 10 + k]);
        P[172 + k] = p; wout[150 + k] = clip1e4(p);
    }
    for (int k = lane; k < 30; k += 32) {
        float p = fmaf(-lr, G5[b * 30 + k], W3[b * 30 + k]);
        int r = k / 10, c = k - r * 10;
        P[184 + 12 * r + c] = p;
        P[224 + 4 * c + r]  = p;                     // W3^T for dg
        wout[160 + k] = clip1e4(p);
    }
    for (int k = lane; k < 3; k += 32) {
        float p = fmaf(-lr, G6[b * 3 + k], b3[b * 3 + k]);
        P[220 + k] = p; wout[190 + k] = clip1e4(p);
    }
    __syncthreads();

    // ---- per-lane slot descriptors for the 193 grad dot-products ----
    // out index == slot. A row in rec; B row in rec, or xsT row (code 100+f).
    int rowA[7], rowB[7];
#pragma unroll
    for (int t = 0; t < 7; t++) {
        int slot = lane + 32 * t;
        int sl = (slot < 193) ? slot : 0;
        int ra, rb;
        if (sl < 40)       { ra = sl >> 2;          rb = 100 + (sl & 3); }   // gW1
        else if (sl < 50)  { ra = sl - 40;          rb = 104; }              // gB1
        else if (sl < 150) { int k = sl - 50; ra = 20 + k / 10; rb = 10 + k % 10; } // gW2
        else if (sl < 160) { ra = 20 + (sl - 150);  rb = 104; }              // gB2
        else if (sl < 190) { int k = sl - 160; ra = 40 + k / 10; rb = 30 + k % 10; } // gW3
        else               { ra = 40 + (sl - 190);  rb = 104; }              // gB3
        rowA[t] = ra; rowB[t] = rb;
    }
    u64 acc[7];
#pragma unroll
    for (int t = 0; t < 7; t++) acc[t] = 0ull;

    float lossacc = 0.f;
    const float invN = 1.f / 150.f;
    const u64* W2p = (const u64*)&P[52];        // rows: 6 u64 stride (12 floats)
    const u64* W3p = (const u64*)&P[184];

    for (int c = 0; c < NCHUNK; c++) {
        const int base = c * CHUNK;

        // ---- fwd+bwd for this chunk; write rows at chunk-local col j ----
        for (int j = lane; j < CHUNK; j += 32) {
            const int s = base + j;
            const float xv0 = xsT[0 * RS + s], xv1 = xsT[1 * RS + s];
            const float xv2 = xsT[2 * RS + s], xv3 = xsT[3 * RS + s];
            const int y = ys[s];

            // layer 1
            float h1[10];
#pragma unroll
            for (int h = 0; h < 10; h++) {
                float4 w = *(const float4*)&P[4 * h];
                float a = fmaf(w.x, xv0, w.y * xv1);
                float d = fmaf(w.z, xv2, w.w * xv3);
                float v = fmaxf(a + d + P[40 + h], 0.f);
                h1[h] = v;
                recW[(10 + h) * RSC + j] = v;            // h1 rows 10..19
            }
            u64 h1p[5];
#pragma unroll
            for (int k = 0; k < 5; k++) h1p[k] = pk(h1[2 * k], h1[2 * k + 1]);

            // layer 2
            float h2[10];
#pragma unroll
            for (int g = 0; g < 10; g++) {
                const u64* r = W2p + 6 * g;
                u64 a = fmul2(r[0], h1p[0]);
                a = ffma2(r[1], h1p[1], a);
                a = ffma2(r[2], h1p[2], a);
                a = ffma2(r[3], h1p[3], a);
                a = ffma2(r[4], h1p[4], a);
                float lo, hi; upk(a, lo, hi);
                float v = fmaxf(lo + hi + P[172 + g], 0.f);
                h2[g] = v;
                recW[(30 + g) * RSC + j] = v;            // h2 rows 30..39
            }
            u64 h2p[5];
#pragma unroll
            for (int k = 0; k < 5; k++) h2p[k] = pk(h2[2 * k], h2[2 * k + 1]);

            // layer 3 logits
            float lg[3];
#pragma unroll
            for (int o = 0; o < 3; o++) {
                const u64* r = W3p + 6 * o;
                u64 a = fmul2(r[0], h2p[0]);
                a = ffma2(r[1], h2p[1], a);
                a = ffma2(r[2], h2p[2], a);
                a = ffma2(r[3], h2p[3], a);
                a = ffma2(r[4], h2p[4], a);
                float lo, hi; upk(a, lo, hi);
                lg[o] = lo + hi + P[220 + o];
            }

            // softmax + CE loss
            float m  = fmaxf(lg[0], fmaxf(lg[1], lg[2]));
            float e0 = __expf(lg[0] - m), e1 = __expf(lg[1] - m), e2 = __expf(lg[2] - m);
            float sum = e0 + e1 + e2;
            float inv = __fdividef(1.f, sum);
            float ly  = (y == 0) ? lg[0] : ((y == 1) ? lg[1] : lg[2]);
            lossacc += (m - ly) + __logf(sum);

            float d0 = (e0 * inv - (y == 0 ? 1.f : 0.f)) * invN;
            float d1 = (e1 * inv - (y == 1 ? 1.f : 0.f)) * invN;
            float d2 = (e2 * inv - (y == 2 ? 1.f : 0.f)) * invN;
            recW[40 * RSC + j] = d0;                     // d rows 40..42
            recW[41 * RSC + j] = d1;
            recW[42 * RSC + j] = d2;

            // backward through layer 2: dg rows + dh1
            u64 dh1p[5];
#pragma unroll
            for (int k = 0; k < 5; k++) dh1p[k] = 0ull;
#pragma unroll
            for (int g = 0; g < 10; g++) {
                float4 wt = *(const float4*)&P[224 + 4 * g];   // W3^T row g
                float dg = fmaf(wt.x, d0, fmaf(wt.y, d1, wt.z * d2));
                dg = (h2[g] > 0.f) ? dg : 0.f;
                recW[(20 + g) * RSC + j] = dg;           // dg rows 20..29
                u64 dgd = pk(dg, dg);
                const u64* r = W2p + 6 * g;
                dh1p[0] = ffma2(dgd, r[0], dh1p[0]);
                dh1p[1] = ffma2(dgd, r[1], dh1p[1]);
                dh1p[2] = ffma2(dgd, r[2], dh1p[2]);
                dh1p[3] = ffma2(dgd, r[3], dh1p[3]);
                dh1p[4] = ffma2(dgd, r[4], dh1p[4]);
            }
            // masked layer-1 deltas -> rows 0..9
#pragma unroll
            for (int k = 0; k < 5; k++) {
                float lo, hi; upk(dh1p[k], lo, hi);
                recW[(2 * k)     * RSC + j] = (h1[2 * k]     > 0.f) ? lo : 0.f;
                recW[(2 * k + 1) * RSC + j] = (h1[2 * k + 1] > 0.f) ? hi : 0.f;
            }
        }
        __syncwarp();

        // ---- accumulate this chunk into the 7 per-lane slot dots ----
#pragma unroll
        for (int t = 0; t < 7; t++) {
            const u64* A = (const u64*)(recW + rowA[t] * RSC);
            const u64* B = (rowB[t] >= 100)
                         ? (const u64*)(xsT + (rowB[t] - 100) * RS + base)
                         : (const u64*)(recW + rowB[t] * RSC);
            u64 a = acc[t];
#pragma unroll
            for (int i = 0; i < CHUNK / 2; i++) {
                a = ffma2(A[i], B[i], a);
            }
            acc[t] = a;
        }
        __syncwarp();   // before next chunk overwrites rows
    }

    // ---- finalize grads, sumsq ----
    float ssq = 0.f;
    float* gout = wout + 193;
#pragma unroll
    for (int t = 0; t < 7; t++) {
        int slot = lane + 32 * t;
        float lo, hi; upk(acc[t], lo, hi);
        float v = lo + hi;
        if (slot < 193) {
            gout[slot] = v;
            ssq = fmaf(v, v, ssq);
        }
    }

    // ---- loss + ssq warp reductions ----
    lossacc += __shfl_xor_sync(0xffffffffu, lossacc, 16);
    lossacc += __shfl_xor_sync(0xffffffffu, lossacc, 8);
    lossacc += __shfl_xor_sync(0xffffffffu, lossacc, 4);
    lossacc += __shfl_xor_sync(0xffffffffu, lossacc, 2);
    lossacc += __shfl_xor_sync(0xffffffffu, lossacc, 1);
    const float loss_b = lossacc * invN;

    ssq += __shfl_xor_sync(0xffffffffu, ssq, 16);
    ssq += __shfl_xor_sync(0xffffffffu, ssq, 8);
    ssq += __shfl_xor_sync(0xffffffffu, ssq, 4);
    ssq += __shfl_xor_sync(0xffffffffu, ssq, 2);
    ssq += __shfl_xor_sync(0xffffffffu, ssq, 1);

    if (lane == 0) {
        atomicAdd(&g_sumsq, ssq);
        wout[386] = loss_b;
        wout[387] = clip1e4(fv[b] - loss_b);
    }
}

// Apply global grad-norm clip coefficient to the grad columns [193, 386).
__global__ void k_scale(float* __restrict__ out) {
    const float coef = fminf(1.f, 10.f / (sqrtf(g_sumsq) + 1e-6f));
    const int b = blockIdx.x;
    const int k = threadIdx.x;
    if (k < 193) {
        size_t idx = (size_t)b * 388 + 193 + k;
        out[idx] *= coef;
    }
}

extern "C" void kernel_launch(void* const* d_in, const int* in_sizes, int n_in,
                              void* d_out, int out_size)
{
    const float* W1 = (const float*)d_in[0];
    const float* b1 = (const float*)d_in[1];
    const float* W2 = (const float*)d_in[2];
    const float* b2 = (const float*)d_in[3];
    const float* W3 = (const float*)d_in[4];
    const float* b3 = (const float*)d_in[5];
    const float* G1 = (const float*)d_in[6];
    const float* G2 = (const float*)d_in[7];
    const float* G3 = (const float*)d_in[8];
    const float* G4 = (const float*)d_in[9];
    const float* G5 = (const float*)d_in[10];
    const float* G6 = (const float*)d_in[11];
    const float* dx = (const float*)d_in[12];
    const float* fv = (const float*)d_in[13];
    const int*   dy = (const int*)d_in[14];
    const int*   ss = (const int*)d_in[15];
    float* out = (float*)d_out;

    const int B = in_sizes[13];   // func_val is [B]

    // Let 8 blocks of 24.4KB static smem co-reside (max carveout).
    static int carveout_set = 0;
    if (!carveout_set) {
        cudaFuncSetAttribute(k_main,
                             cudaFuncAttributePreferredSharedMemoryCarveout,
                             cudaSharedmemCarveoutMaxShared);
        carveout_set = 1;
    }

    // g_sumsq is 0 on entry: static init on first call, k_zero (below) after.
    k_main<<<B / WPB, BDIM>>>(W1, b1, W2, b2, W3, b3,
                              G1, G2, G3, G4, G5, G6,
                              dx, fv, dy, ss, out);
    k_scale<<<B, 224>>>(out);
    k_zero<<<1, 1>>>();          // reset for the next (graph-replayed) call
}

// round 5
// speedup vs baseline: 1.2402x; 1.2402x over previous
#include <cuda_runtime.h>

#define BDIM 64
#define WPB 2             // warps (MLPs) per block
#define XST 192           // xsT row stride (floats)
#define RSC 66            // rec row stride (floats), even, >=64, conflict-safe
#define CHUNK 64          // samples per chunk (32 pairs = 32 lanes)
#define NCHUNK 3          // 192 = padded sample count
#define NROWS 43          // rec rows: dhm[10] h1[10] dg[10] h2[10] d[3]
#define RECW (NROWS * RSC)
#define PSTRIDE 264
#define NS 150

typedef unsigned long long u64;

__constant__ float c_lr[6] = {0.001f, 0.01f, 0.05f, 0.1f, 0.5f, 1.0f};
__device__ float g_sumsq = 0.f;   // zeroed by k_zero at END of each call

__device__ __forceinline__ float clip1e4(float v) {
    return fminf(fmaxf(v, -10000.f), 10000.f);
}
__device__ __forceinline__ u64 pk(float lo, float hi) {
    u64 r; asm("mov.b64 %0, {%1,%2};" : "=l"(r) : "f"(lo), "f"(hi)); return r;
}
__device__ __forceinline__ u64 dup(float v) {
    u64 r; asm("mov.b64 %0, {%1,%1};" : "=l"(r) : "f"(v)); return r;
}
__device__ __forceinline__ void upk(u64 v, float& lo, float& hi) {
    asm("mov.b64 {%0,%1}, %2;" : "=f"(lo), "=f"(hi) : "l"(v));
}
__device__ __forceinline__ u64 ffma2(u64 a, u64 b, u64 c) {
    u64 d; asm("fma.rn.f32x2 %0, %1, %2, %3;" : "=l"(d) : "l"(a), "l"(b), "l"(c));
    return d;
}
__device__ __forceinline__ u64 fmul2(u64 a, u64 b) {
    u64 d; asm("mul.rn.f32x2 %0, %1, %2;" : "=l"(d) : "l"(a), "l"(b)); return d;
}

__global__ void k_zero() { g_sumsq = 0.f; }

__global__ void __launch_bounds__(BDIM, 7) k_main(
    const float* __restrict__ W1, const float* __restrict__ b1,
    const float* __restrict__ W2, const float* __restrict__ b2,
    const float* __restrict__ W3, const float* __restrict__ b3,
    const float* __restrict__ G1, const float* __restrict__ G2,
    const float* __restrict__ G3, const float* __restrict__ G4,
    const float* __restrict__ G5, const float* __restrict__ G6,
    const float* __restrict__ dx, const float* __restrict__ fv,
    const int* __restrict__ dy, const int* __restrict__ ss,
    float* __restrict__ out)
{
    __shared__ __align__(16) float xsT[4 * XST];   // x features, transposed
    __shared__ __align__(16) float ones64[CHUNK];  // ones row for bias sums
    __shared__ __align__(16) float ps[WPB * PSTRIDE];
    __shared__ __align__(16) float rec[WPB * RECW];

    const int tid  = threadIdx.x;
    const int lane = tid & 31;
    const int warp = tid >> 5;
    const int b    = blockIdx.x * WPB + warp;

    for (int i = tid; i < XST; i += BDIM) {
        if (i < NS) {
            float4 xv = ((const float4*)dx)[i];
            xsT[0 * XST + i] = xv.x;
            xsT[1 * XST + i] = xv.y;
            xsT[2 * XST + i] = xv.z;
            xsT[3 * XST + i] = xv.w;
        } else {
            xsT[0 * XST + i] = 0.f;
            xsT[1 * XST + i] = 0.f;
            xsT[2 * XST + i] = 0.f;
            xsT[3 * XST + i] = 0.f;
        }
    }
    if (tid < CHUNK) ones64[tid] = 1.f;

    float* P    = ps  + warp * PSTRIDE;
    float* recW = rec + warp * RECW;
    // P layout: 0:W1[10x4] 40:b1[10] 52:W2 rows stride 12 (10 rows)
    // 172:b2[10] 184:W3 rows stride 12 (3 rows) 220:b3[3] 224:W3^T stride 4

    const float lr = c_lr[ss[b]];
    float* wout = out + (size_t)b * 388;

    // zero P (covers all row pads), then fill
    for (int k = lane; k < PSTRIDE; k += 32) P[k] = 0.f;
    __syncwarp();
    for (int k = lane; k < 40; k += 32) {
        float p = fmaf(-lr, G1[b * 40 + k], W1[b * 40 + k]);
        P[k] = p; wout[k] = clip1e4(p);
    }
    for (int k = lane; k < 10; k += 32) {
        float p = fmaf(-lr, G2[b * 10 + k], b1[b * 10 + k]);
        P[40 + k] = p; wout[40 + k] = clip1e4(p);
    }
    for (int k = lane; k < 100; k += 32) {
        float p = fmaf(-lr, G3[b * 100 + k], W2[b * 100 + k]);
        int r = k / 10, c = k - r * 10;
        P[52 + 12 * r + c] = p; wout[50 + k] = clip1e4(p);
    }
    for (int k = lane; k < 10; k += 32) {
        float p = fmaf(-lr, G4[b * 10 + k], b2[b * 10 + k]);
        P[172 + k] = p; wout[150 + k] = clip1e4(p);
    }
    for (int k = lane; k < 30; k += 32) {
        float p = fmaf(-lr, G5[b * 30 + k], W3[b * 30 + k]);
        int r = k / 10, c = k - r * 10;
        P[184 + 12 * r + c] = p;
        P[224 + 4 * c + r]  = p;                 // W3^T (rows stride 4)
        wout[160 + k] = clip1e4(p);
    }
    for (int k = lane; k < 3; k += 32) {
        float p = fmaf(-lr, G6[b * 3 + k], b3[b * 3 + k]);
        P[220 + k] = p; wout[190 + k] = clip1e4(p);
    }
    __syncthreads();

    // ---- minipass descriptors ----
    // Phase A: gW2 (100 dots) as 2x2 outer-product tiles on lanes 0..24.
    const int qA = (lane < 25) ? lane / 5 : 0;
    const int rA = (lane < 25) ? lane % 5 : 0;
    const u64* pa0 = (const u64*)&recW[(20 + 2 * qA) * RSC];
    const u64* pa1 = (const u64*)&recW[(21 + 2 * qA) * RSC];
    const u64* pb0 = (const u64*)&recW[(10 + 2 * rA) * RSC];
    const u64* pb1 = (const u64*)&recW[(11 + 2 * rA) * RSC];
    u64 accA0 = 0ull, accA1 = 0ull, accA2 = 0ull, accA3 = 0ull;

    // Phase B: 93 remaining dots, branchless A.B with ones-row for sums.
    // slots: 0..39 gW1 | 40..49 gB1 | 50..59 gB2 | 60..89 gW3 | 90..92 gB3
    const u64* ArB[3]; const u64* BpB[3]; int badv[3], oidx[3]; bool bval[3];
#pragma unroll
    for (int t = 0; t < 3; t++) {
        int sl = lane + 32 * t;
        bval[t] = (sl < 93);
        int s = bval[t] ? sl : 0;
        int ra; const float* bp; int adv = 0;
        if (s < 40)      { ra = s >> 2;        bp = &xsT[(s & 3) * XST]; adv = CHUNK / 2; }
        else if (s < 50) { ra = s - 40;        bp = ones64; }
        else if (s < 60) { ra = 20 + (s - 50); bp = ones64; }
        else if (s < 90) { int k = s - 60; ra = 40 + k / 10; bp = &recW[(30 + k % 10) * RSC]; }
        else             { ra = 40 + (s - 90); bp = ones64; }
        ArB[t]  = (const u64*)&recW[ra * RSC];
        BpB[t]  = (const u64*)bp;
        badv[t] = adv;
        oidx[t] = (s < 50) ? s : s + 100;
    }
    u64 accB[3] = {0ull, 0ull, 0ull};

    float l0acc = 0.f, l1acc = 0.f;
    const float invN = 1.f / 150.f;
    const int cj = 2 * lane;   // chunk-local column of this lane's sample pair

#pragma unroll 1
    for (int c = 0; c < NCHUNK; c++) {
        const int base = c * CHUNK;
        const int s0 = base + cj;
        const bool m0 = (s0 < NS);
        const bool m1 = (s0 + 1 < NS);
        int2 y01 = m0 ? *(const int2*)&dy[s0] : make_int2(0, 0);
        const u64 x0 = *(const u64*)&xsT[0 * XST + s0];
        const u64 x1 = *(const u64*)&xsT[1 * XST + s0];
        const u64 x2 = *(const u64*)&xsT[2 * XST + s0];
        const u64 x3 = *(const u64*)&xsT[3 * XST + s0];

        // layer 1 (packed across the sample pair)
        u64 h1p[10];
#pragma unroll
        for (int h = 0; h < 10; h++) {
            float4 w = *(const float4*)&P[4 * h];
            u64 a = fmul2(dup(w.x), x0);
            a = ffma2(dup(w.y), x1, a);
            a = ffma2(dup(w.z), x2, a);
            a = ffma2(dup(w.w), x3, a);
            float lo, hi; upk(a, lo, hi);
            float bb = P[40 + h];
            lo = fmaxf(lo + bb, 0.f);
            hi = fmaxf(hi + bb, 0.f);
            u64 v = pk(lo, hi);
            h1p[h] = v;
            *(u64*)&recW[(10 + h) * RSC + cj] = v;
        }
        // layer 2
        u64 h2p[10];
#pragma unroll
        for (int g = 0; g < 10; g++) {
            const float* r = &P[52 + 12 * g];
            float4 wa = *(const float4*)r;
            float4 wb = *(const float4*)(r + 4);
            float2 wc = *(const float2*)(r + 8);
            u64 a = fmul2(dup(wa.x), h1p[0]);
            a = ffma2(dup(wa.y), h1p[1], a);
            a = ffma2(dup(wa.z), h1p[2], a);
            a = ffma2(dup(wa.w), h1p[3], a);
            a = ffma2(dup(wb.x), h1p[4], a);
            a = ffma2(dup(wb.y), h1p[5], a);
            a = ffma2(dup(wb.z), h1p[6], a);
            a = ffma2(dup(wb.w), h1p[7], a);
            a = ffma2(dup(wc.x), h1p[8], a);
            a = ffma2(dup(wc.y), h1p[9], a);
            float lo, hi; upk(a, lo, hi);
            float bb = P[172 + g];
            lo = fmaxf(lo + bb, 0.f);
            hi = fmaxf(hi + bb, 0.f);
            u64 v = pk(lo, hi);
            h2p[g] = v;
            *(u64*)&recW[(30 + g) * RSC + cj] = v;
        }
        // layer 3 logits
        float lgl[3], lgh[3];
#pragma unroll
        for (int o = 0; o < 3; o++) {
            const float* r = &P[184 + 12 * o];
            float4 wa = *(const float4*)r;
            float4 wb = *(const float4*)(r + 4);
            float2 wc = *(const float2*)(r + 8);
            u64 a = fmul2(dup(wa.x), h2p[0]);
            a = ffma2(dup(wa.y), h2p[1], a);
            a = ffma2(dup(wa.z), h2p[2], a);
            a = ffma2(dup(wa.w), h2p[3], a);
            a = ffma2(dup(wb.x), h2p[4], a);
            a = ffma2(dup(wb.y), h2p[5], a);
            a = ffma2(dup(wb.z), h2p[6], a);
            a = ffma2(dup(wb.w), h2p[7], a);
            a = ffma2(dup(wc.x), h2p[8], a);
            a = ffma2(dup(wc.y), h2p[9], a);
            float lo, hi; upk(a, lo, hi);
            float bb = P[220 + o];
            lgl[o] = lo + bb;
            lgh[o] = hi + bb;
        }
        // softmax + CE (per half, masked for padding)
        float d00, d01, d02, d10, d11, d12;
        {
            float mm = fmaxf(lgl[0], fmaxf(lgl[1], lgl[2]));
            float e0 = __expf(lgl[0] - mm), e1 = __expf(lgl[1] - mm), e2 = __expf(lgl[2] - mm);
            float sm = e0 + e1 + e2, iv = __fdividef(1.f, sm);
            int y = y01.x;
            float ly = (y == 0) ? lgl[0] : ((y == 1) ? lgl[1] : lgl[2]);
            l0acc += m0 ? ((mm - ly) + __logf(sm)) : 0.f;
            float k0 = m0 ? invN : 0.f;
            d00 = (e0 * iv - (y == 0 ? 1.f : 0.f)) * k0;
            d01 = (e1 * iv - (y == 1 ? 1.f : 0.f)) * k0;
            d02 = (e2 * iv - (y == 2 ? 1.f : 0.f)) * k0;
        }
        {
            float mm = fmaxf(lgh[0], fmaxf(lgh[1], lgh[2]));
            float e0 = __expf(lgh[0] - mm), e1 = __expf(lgh[1] - mm), e2 = __expf(lgh[2] - mm);
            float sm = e0 + e1 + e2, iv = __fdividef(1.f, sm);
            int y = y01.y;
            float ly = (y == 0) ? lgh[0] : ((y == 1) ? lgh[1] : lgh[2]);
            l1acc += m1 ? ((mm - ly) + __logf(sm)) : 0.f;
            float k1 = m1 ? invN : 0.f;
            d10 = (e0 * iv - (y == 0 ? 1.f : 0.f)) * k1;
            d11 = (e1 * iv - (y == 1 ? 1.f : 0.f)) * k1;
            d12 = (e2 * iv - (y == 2 ? 1.f : 0.f)) * k1;
        }
        u64 d0p = pk(d00, d10), d1p = pk(d01, d11), d2p = pk(d02, d12);
        *(u64*)&recW[40 * RSC + cj] = d0p;
        *(u64*)&recW[41 * RSC + cj] = d1p;
        *(u64*)&recW[42 * RSC + cj] = d2p;

        // backward: dg rows (masked), dh1 accumulation
        u64 dh[10];
#pragma unroll
        for (int h = 0; h < 10; h++) dh[h] = 0ull;
#pragma unroll
        for (int g = 0; g < 10; g++) {
            float4 wt = *(const float4*)&P[224 + 4 * g];
            u64 dg = fmul2(dup(wt.x), d0p);
            dg = ffma2(dup(wt.y), d1p, dg);
            dg = ffma2(dup(wt.z), d2p, dg);
            {
                float vl, vh, rl, rh; upk(dg, vl, vh); upk(h2p[g], rl, rh);
                vl = (rl > 0.f) ? vl : 0.f;
                vh = (rh > 0.f) ? vh : 0.f;
                dg = pk(vl, vh);
            }
            *(u64*)&recW[(20 + g) * RSC + cj] = dg;
            const float* r = &P[52 + 12 * g];
            float4 wa = *(const float4*)r;
            float4 wb = *(const float4*)(r + 4);
            float2 wc = *(const float2*)(r + 8);
            dh[0] = ffma2(dup(wa.x), dg, dh[0]);
            dh[1] = ffma2(dup(wa.y), dg, dh[1]);
            dh[2] = ffma2(dup(wa.z), dg, dh[2]);
            dh[3] = ffma2(dup(wa.w), dg, dh[3]);
            dh[4] = ffma2(dup(wb.x), dg, dh[4]);
            dh[5] = ffma2(dup(wb.y), dg, dh[5]);
            dh[6] = ffma2(dup(wb.z), dg, dh[6]);
            dh[7] = ffma2(dup(wb.w), dg, dh[7]);
            dh[8] = ffma2(dup(wc.x), dg, dh[8]);
            dh[9] = ffma2(dup(wc.y), dg, dh[9]);
        }
#pragma unroll
        for (int h = 0; h < 10; h++) {
            float vl, vh, rl, rh; upk(dh[h], vl, vh); upk(h1p[h], rl, rh);
            vl = (rl > 0.f) ? vl : 0.f;
            vh = (rh > 0.f) ? vh : 0.f;
            *(u64*)&recW[h * RSC + cj] = pk(vl, vh);
        }
        __syncwarp();

        // ---- minipass phase A: 2x2 gW2 tiles ----
        {
            u64 t00 = accA0, t01 = accA1, t10 = accA2, t11 = accA3;
#pragma unroll
            for (int i = 0; i < CHUNK / 2; i++) {
                u64 A0 = pa0[i], A1 = pa1[i], B0 = pb0[i], B1 = pb1[i];
                t00 = ffma2(A0, B0, t00);
                t01 = ffma2(A0, B1, t01);
                t10 = ffma2(A1, B0, t10);
                t11 = ffma2(A1, B1, t11);
            }
            accA0 = t00; accA1 = t01; accA2 = t10; accA3 = t11;
        }
        // ---- minipass phase B: 93 slot dots ----
#pragma unroll
        for (int t = 0; t < 3; t++) {
            const u64* A = ArB[t];
            const u64* B = BpB[t];
            u64 a = accB[t];
#pragma unroll
            for (int i = 0; i < CHUNK / 2; i++) a = ffma2(A[i], B[i], a);
            accB[t] = a;
            BpB[t] = B + badv[t];
        }
        __syncwarp();   // before next chunk overwrites rec rows
    }

    // ---- finalize grads, sumsq ----
    float ssq = 0.f;
    float* gout = wout + 193;
    if (lane < 25) {
        int r0 = (2 * qA) * 10 + 2 * rA;   // gW2 flat index of tile corner
        float lo, hi, v;
        upk(accA0, lo, hi); v = lo + hi; gout[50 + r0]      = v; ssq = fmaf(v, v, ssq);
        upk(accA1, lo, hi); v = lo + hi; gout[50 + r0 + 1]  = v; ssq = fmaf(v, v, ssq);
        upk(accA2, lo, hi); v = lo + hi; gout[50 + r0 + 10] = v; ssq = fmaf(v, v, ssq);
        upk(accA3, lo, hi); v = lo + hi; gout[50 + r0 + 11] = v; ssq = fmaf(v, v, ssq);
    }
#pragma unroll
    for (int t = 0; t < 3; t++) {
        if (bval[t]) {
            float lo, hi; upk(accB[t], lo, hi);
            float v = lo + hi;
            gout[oidx[t]] = v;
            ssq = fmaf(v, v, ssq);
        }
    }

    float lossacc = l0acc + l1acc;
    lossacc += __shfl_xor_sync(0xffffffffu, lossacc, 16);
    lossacc += __shfl_xor_sync(0xffffffffu, lossacc, 8);
    lossacc += __shfl_xor_sync(0xffffffffu, lossacc, 4);
    lossacc += __shfl_xor_sync(0xffffffffu, lossacc, 2);
    lossacc += __shfl_xor_sync(0xffffffffu, lossacc, 1);
    const float loss_b = lossacc * invN;

    ssq += __shfl_xor_sync(0xffffffffu, ssq, 16);
    ssq += __shfl_xor_sync(0xffffffffu, ssq, 8);
    ssq += __shfl_xor_sync(0xffffffffu, ssq, 4);
    ssq += __shfl_xor_sync(0xffffffffu, ssq, 2);
    ssq += __shfl_xor_sync(0xffffffffu, ssq, 1);

    if (lane == 0) {
        atomicAdd(&g_sumsq, ssq);
        wout[386] = loss_b;
        wout[387] = clip1e4(fv[b] - loss_b);
    }
}

// Apply global grad-norm clip coefficient to the grad columns [193, 386).
__global__ void k_scale(float* __restrict__ out) {
    const float coef = fminf(1.f, 10.f / (sqrtf(g_sumsq) + 1e-6f));
    const int b = blockIdx.x;
    const int k = threadIdx.x;
    if (k < 193) {
        size_t idx = (size_t)b * 388 + 193 + k;
        out[idx] *= coef;
    }
}

extern "C" void kernel_launch(void* const* d_in, const int* in_sizes, int n_in,
                              void* d_out, int out_size)
{
    const float* W1 = (const float*)d_in[0];
    const float* b1 = (const float*)d_in[1];
    const float* W2 = (const float*)d_in[2];
    const float* b2 = (const float*)d_in[3];
    const float* W3 = (const float*)d_in[4];
    const float* b3 = (const float*)d_in[5];
    const float* G1 = (const float*)d_in[6];
    const float* G2 = (const float*)d_in[7];
    const float* G3 = (const float*)d_in[8];
    const float* G4 = (const float*)d_in[9];
    const float* G5 = (const float*)d_in[10];
    const float* G6 = (const float*)d_in[11];
    const float* dx = (const float*)d_in[12];
    const float* fv = (const float*)d_in[13];
    const int*   dy = (const int*)d_in[14];
    const int*   ss = (const int*)d_in[15];
    float* out = (float*)d_out;

    const int B = in_sizes[13];   // func_val is [B]

    static int carveout_set = 0;
    if (!carveout_set) {
        cudaFuncSetAttribute(k_main,
                             cudaFuncAttributePreferredSharedMemoryCarveout,
                             cudaSharedmemCarveoutMaxShared);
        carveout_set = 1;
    }

    // g_sumsq is 0 on entry: static init on first call, k_zero (below) after.
    k_main<<<B / WPB, BDIM>>>(W1, b1, W2, b2, W3, b3,
                              G1, G2, G3, G4, G5, G6,
                              dx, fv, dy, ss, out);
    k_scale<<<B, 224>>>(out);
    k_zero<<<1, 1>>>();          // reset for the next (graph-replayed) call
}

// round 6
// speedup vs baseline: 1.4910x; 1.2023x over previous
#include <cuda_runtime.h>

#define BDIM 64
#define WPB 2             // warps (MLPs) per block
#define XST 194           // xsT row stride (floats); 194%32=2 -> distinct banks
#define RSC 66            // rec row stride (floats); 66%32=2 -> distinct banks
#define CHUNK 64          // samples per chunk (32 lanes x 1 pair)
#define NCHUNK 3          // 192 padded samples
#define NROWS 43          // rec rows: dhm[10] h1[10] dg[10] h2[10] d[3]
#define RECW (NROWS * RSC)
#define PSTRIDE 264
#define NS 150

typedef unsigned long long u64;

__constant__ float c_lr[6] = {0.001f, 0.01f, 0.05f, 0.1f, 0.5f, 1.0f};
__device__ float g_sumsq = 0.f;   // zeroed by k_zero at END of each call

__device__ __forceinline__ float clip1e4(float v) {
    return fminf(fmaxf(v, -10000.f), 10000.f);
}
__device__ __forceinline__ u64 pk(float lo, float hi) {
    u64 r; asm("mov.b64 %0, {%1,%2};" : "=l"(r) : "f"(lo), "f"(hi)); return r;
}
__device__ __forceinline__ u64 dup(float v) {
    u64 r; asm("mov.b64 %0, {%1,%1};" : "=l"(r) : "f"(v)); return r;
}
__device__ __forceinline__ void upk(u64 v, float& lo, float& hi) {
    asm("mov.b64 {%0,%1}, %2;" : "=f"(lo), "=f"(hi) : "l"(v));
}
__device__ __forceinline__ u64 ffma2(u64 a, u64 b, u64 c) {
    u64 d; asm("fma.rn.f32x2 %0, %1, %2, %3;" : "=l"(d) : "l"(a), "l"(b), "l"(c));
    return d;
}
__device__ __forceinline__ u64 fmul2(u64 a, u64 b) {
    u64 d; asm("mul.rn.f32x2 %0, %1, %2;" : "=l"(d) : "l"(a), "l"(b)); return d;
}

__global__ void k_zero() { g_sumsq = 0.f; }

__global__ void __launch_bounds__(BDIM, 7) k_main(
    const float* __restrict__ W1, const float* __restrict__ b1,
    const float* __restrict__ W2, const float* __restrict__ b2,
    const float* __restrict__ W3, const float* __restrict__ b3,
    const float* __restrict__ G1, const float* __restrict__ G2,
    const float* __restrict__ G3, const float* __restrict__ G4,
    const float* __restrict__ G5, const float* __restrict__ G6,
    const float* __restrict__ dx, const float* __restrict__ fv,
    const int* __restrict__ dy, const int* __restrict__ ss,
    float* __restrict__ out)
{
    __shared__ __align__(16) float xsT[4 * XST];   // x features, transposed
    __shared__ __align__(16) float ones64[CHUNK];  // ones row for bias sums
    __shared__ __align__(16) float ps[WPB * PSTRIDE];
    __shared__ __align__(16) float rec[WPB * RECW];

    const int tid  = threadIdx.x;
    const int lane = tid & 31;
    const int warp = tid >> 5;
    const int b    = blockIdx.x * WPB + warp;

    for (int i = tid; i < XST; i += BDIM) {
        if (i < NS) {
            float4 xv = ((const float4*)dx)[i];
            xsT[0 * XST + i] = xv.x;
            xsT[1 * XST + i] = xv.y;
            xsT[2 * XST + i] = xv.z;
            xsT[3 * XST + i] = xv.w;
        } else {
            xsT[0 * XST + i] = 0.f;
            xsT[1 * XST + i] = 0.f;
            xsT[2 * XST + i] = 0.f;
            xsT[3 * XST + i] = 0.f;
        }
    }
    if (tid < CHUNK) ones64[tid] = 1.f;

    float* P    = ps  + warp * PSTRIDE;
    float* recW = rec + warp * RECW;
    // P layout: 0:W1[10x4] 40:b1[10] 52:W2 rows stride 12 (10 rows)
    // 172:b2[10] 184:W3 rows stride 12 (3 rows) 220:b3[3] 224:W3^T stride 4

    const float lr = c_lr[ss[b]];
    float* wout = out + (size_t)b * 388;

    for (int k = lane; k < PSTRIDE; k += 32) P[k] = 0.f;
    __syncwarp();
    for (int k = lane; k < 40; k += 32) {
        float p = fmaf(-lr, G1[b * 40 + k], W1[b * 40 + k]);
        P[k] = p; wout[k] = clip1e4(p);
    }
    for (int k = lane; k < 10; k += 32) {
        float p = fmaf(-lr, G2[b * 10 + k], b1[b * 10 + k]);
        P[40 + k] = p; wout[40 + k] = clip1e4(p);
    }
    for (int k = lane; k < 100; k += 32) {
        float p = fmaf(-lr, G3[b * 100 + k], W2[b * 100 + k]);
        int r = k / 10, c = k - r * 10;
        P[52 + 12 * r + c] = p; wout[50 + k] = clip1e4(p);
    }
    for (int k = lane; k < 10; k += 32) {
        float p = fmaf(-lr, G4[b * 10 + k], b2[b * 10 + k]);
        P[172 + k] = p; wout[150 + k] = clip1e4(p);
    }
    for (int k = lane; k < 30; k += 32) {
        float p = fmaf(-lr, G5[b * 30 + k], W3[b * 30 + k]);
        int r = k / 10, c = k - r * 10;
        P[184 + 12 * r + c] = p;
        P[224 + 4 * c + r]  = p;                 // W3^T (rows stride 4)
        wout[160 + k] = clip1e4(p);
    }
    for (int k = lane; k < 3; k += 32) {
        float p = fmaf(-lr, G6[b * 3 + k], b3[b * 3 + k]);
        P[220 + k] = p; wout[190 + k] = clip1e4(p);
    }
    __syncthreads();

    // ================= minipass tile descriptors =================
    int id[8];
#pragma unroll
    for (int k = 0; k < 8; k++) id[k] = -1;

    // tile-set 1: gW2 (10x10) as 5x5 pair-tiles on lanes 0..24
    const int t1v = (lane < 25);
    const int q5 = t1v ? lane / 5 : 0;
    const int r5 = t1v ? lane % 5 : 0;
    const u64* t1a0 = (const u64*)&recW[(20 + 2 * q5) * RSC];  // dg rows
    const u64* t1a1 = (const u64*)&recW[(21 + 2 * q5) * RSC];
    const u64* t1b0 = (const u64*)&recW[(10 + 2 * r5) * RSC];  // h1 rows
    const u64* t1b1 = (const u64*)&recW[(11 + 2 * r5) * RSC];
    if (t1v) {
        int base = 50 + 20 * q5 + 2 * r5;      // gW2 flat -> gout 50..149
        id[0] = base; id[1] = base + 1; id[2] = base + 10; id[3] = base + 11;
    }

    // tile-set 2: lanes 0..9 gW1, 10..19 gW3, 20..31 bias sums
    const u64 *t2a0, *t2a1, *t2b0, *t2b1;
    int t2adv = 0;
    if (lane < 10) {
        int a = lane >> 1, bq = lane & 1;
        t2a0 = (const u64*)&recW[(2 * a) * RSC];        // dhm rows
        t2a1 = (const u64*)&recW[(2 * a + 1) * RSC];
        t2b0 = (const u64*)&xsT[(2 * bq) * XST];        // x rows
        t2b1 = (const u64*)&xsT[(2 * bq + 1) * XST];
        t2adv = CHUNK / 2;
        int base = 8 * a + 2 * bq;                      // gW1 -> gout 0..39
        id[4] = base; id[5] = base + 1; id[6] = base + 4; id[7] = base + 5;
    } else if (lane < 20) {
        int l = lane - 10, p = l / 5, qh = l % 5;
        t2a0 = (const u64*)&recW[(40 + 2 * p) * RSC];   // d rows (o=2p)
        t2a1 = (const u64*)&recW[((p == 0) ? 41 : 42) * RSC];
        t2b0 = (const u64*)&recW[(30 + 2 * qh) * RSC];  // h2 rows
        t2b1 = (const u64*)&recW[(31 + 2 * qh) * RSC];
        int base = 160 + 20 * p + 2 * qh;               // gW3 -> gout 160..189
        id[4] = base; id[5] = base + 1;
        if (p == 0) { id[6] = base + 10; id[7] = base + 11; }
    } else {
        int l = lane - 20;                              // 0..11
        int k0 = 2 * l, k1 = 2 * l + 1;                 // bias list 0..23
        int r0 = (k0 < 10) ? k0 : ((k0 < 20) ? k0 + 10 : ((k0 < 23) ? k0 + 20 : 40));
        int r1 = (k1 < 10) ? k1 : ((k1 < 20) ? k1 + 10 : ((k1 < 23) ? k1 + 20 : 40));
        t2a0 = (const u64*)&recW[r0 * RSC];
        t2a1 = (const u64*)&recW[r1 * RSC];
        t2b0 = (const u64*)ones64;
        t2b1 = (const u64*)ones64;
        id[4] = (k0 < 10) ? 40 + k0 : ((k0 < 20) ? 140 + k0 : ((k0 < 23) ? 170 + k0 : -1));
        id[6] = (k1 < 10) ? 40 + k1 : ((k1 < 20) ? 140 + k1 : ((k1 < 23) ? 170 + k1 : -1));
    }

    u64 m0a = 0ull, m1a = 0ull, m2a = 0ull, m3a = 0ull;   // tile1 accs
    u64 m4a = 0ull, m5a = 0ull, m6a = 0ull, m7a = 0ull;   // tile2 accs

    float l0acc = 0.f, l1acc = 0.f;
    const float invN = 1.f / 150.f;
    const int cj = 2 * lane;   // chunk-local column of this lane's sample pair

#pragma unroll 1
    for (int c = 0; c < NCHUNK; c++) {
        const int base = c * CHUNK;
        const int s0 = base + cj;
        const bool msk0 = (s0 < NS);
        const bool msk1 = (s0 + 1 < NS);
        int2 y01 = msk0 ? *(const int2*)&dy[s0] : make_int2(0, 0);
        const u64 x0 = *(const u64*)&xsT[0 * XST + s0];
        const u64 x1 = *(const u64*)&xsT[1 * XST + s0];
        const u64 x2 = *(const u64*)&xsT[2 * XST + s0];
        const u64 x3 = *(const u64*)&xsT[3 * XST + s0];

        // layer 1 (packed across the sample pair)
        u64 h1p[10];
#pragma unroll
        for (int h = 0; h < 10; h++) {
            float4 w = *(const float4*)&P[4 * h];
            u64 a = fmul2(dup(w.x), x0);
            a = ffma2(dup(w.y), x1, a);
            a = ffma2(dup(w.z), x2, a);
            a = ffma2(dup(w.w), x3, a);
            float lo, hi; upk(a, lo, hi);
            float bb = P[40 + h];
            lo = fmaxf(lo + bb, 0.f);
            hi = fmaxf(hi + bb, 0.f);
            u64 v = pk(lo, hi);
            h1p[h] = v;
            *(u64*)&recW[(10 + h) * RSC + cj] = v;
        }
        // layer 2
        u64 h2p[10];
#pragma unroll
        for (int g = 0; g < 10; g++) {
            const float* r = &P[52 + 12 * g];
            float4 wa = *(const float4*)r;
            float4 wb = *(const float4*)(r + 4);
            float2 wc = *(const float2*)(r + 8);
            u64 a = fmul2(dup(wa.x), h1p[0]);
            a = ffma2(dup(wa.y), h1p[1], a);
            a = ffma2(dup(wa.z), h1p[2], a);
            a = ffma2(dup(wa.w), h1p[3], a);
            a = ffma2(dup(wb.x), h1p[4], a);
            a = ffma2(dup(wb.y), h1p[5], a);
            a = ffma2(dup(wb.z), h1p[6], a);
            a = ffma2(dup(wb.w), h1p[7], a);
            a = ffma2(dup(wc.x), h1p[8], a);
            a = ffma2(dup(wc.y), h1p[9], a);
            float lo, hi; upk(a, lo, hi);
            float bb = P[172 + g];
            lo = fmaxf(lo + bb, 0.f);
            hi = fmaxf(hi + bb, 0.f);
            u64 v = pk(lo, hi);
            h2p[g] = v;
            *(u64*)&recW[(30 + g) * RSC + cj] = v;
        }
        // layer 3 logits
        float lgl[3], lgh[3];
#pragma unroll
        for (int o = 0; o < 3; o++) {
            const float* r = &P[184 + 12 * o];
            float4 wa = *(const float4*)r;
            float4 wb = *(const float4*)(r + 4);
            float2 wc = *(const float2*)(r + 8);
            u64 a = fmul2(dup(wa.x), h2p[0]);
            a = ffma2(dup(wa.y), h2p[1], a);
            a = ffma2(dup(wa.z), h2p[2], a);
            a = ffma2(dup(wa.w), h2p[3], a);
            a = ffma2(dup(wb.x), h2p[4], a);
            a = ffma2(dup(wb.y), h2p[5], a);
            a = ffma2(dup(wb.z), h2p[6], a);
            a = ffma2(dup(wb.w), h2p[7], a);
            a = ffma2(dup(wc.x), h2p[8], a);
            a = ffma2(dup(wc.y), h2p[9], a);
            float lo, hi; upk(a, lo, hi);
            float bb = P[220 + o];
            lgl[o] = lo + bb;
            lgh[o] = hi + bb;
        }
        // softmax + CE (per half, masked for padding)
        float d00, d01, d02, d10, d11, d12;
        {
            float mm = fmaxf(lgl[0], fmaxf(lgl[1], lgl[2]));
            float e0 = __expf(lgl[0] - mm), e1 = __expf(lgl[1] - mm), e2 = __expf(lgl[2] - mm);
            float sm = e0 + e1 + e2, iv = __fdividef(1.f, sm);
            int y = y01.x;
            float ly = (y == 0) ? lgl[0] : ((y == 1) ? lgl[1] : lgl[2]);
            l0acc += msk0 ? ((mm - ly) + __logf(sm)) : 0.f;
            float k0 = msk0 ? invN : 0.f;
            d00 = (e0 * iv - (y == 0 ? 1.f : 0.f)) * k0;
            d01 = (e1 * iv - (y == 1 ? 1.f : 0.f)) * k0;
            d02 = (e2 * iv - (y == 2 ? 1.f : 0.f)) * k0;
        }
        {
            float mm = fmaxf(lgh[0], fmaxf(lgh[1], lgh[2]));
            float e0 = __expf(lgh[0] - mm), e1 = __expf(lgh[1] - mm), e2 = __expf(lgh[2] - mm);
            float sm = e0 + e1 + e2, iv = __fdividef(1.f, sm);
            int y = y01.y;
            float ly = (y == 0) ? lgh[0] : ((y == 1) ? lgh[1] : lgh[2]);
            l1acc += msk1 ? ((mm - ly) + __logf(sm)) : 0.f;
            float k1 = msk1 ? invN : 0.f;
            d10 = (e0 * iv - (y == 0 ? 1.f : 0.f)) * k1;
            d11 = (e1 * iv - (y == 1 ? 1.f : 0.f)) * k1;
            d12 = (e2 * iv - (y == 2 ? 1.f : 0.f)) * k1;
        }
        u64 d0p = pk(d00, d10), d1p = pk(d01, d11), d2p = pk(d02, d12);
        *(u64*)&recW[40 * RSC + cj] = d0p;
        *(u64*)&recW[41 * RSC + cj] = d1p;
        *(u64*)&recW[42 * RSC + cj] = d2p;

        // backward: dg rows (masked), dh1 accumulation
        u64 dh[10];
#pragma unroll
        for (int h = 0; h < 10; h++) dh[h] = 0ull;
#pragma unroll
        for (int g = 0; g < 10; g++) {
            float4 wt = *(const float4*)&P[224 + 4 * g];
            u64 dg = fmul2(dup(wt.x), d0p);
            dg = ffma2(dup(wt.y), d1p, dg);
            dg = ffma2(dup(wt.z), d2p, dg);
            {
                float vl, vh, rl, rh; upk(dg, vl, vh); upk(h2p[g], rl, rh);
                vl = (rl > 0.f) ? vl : 0.f;
                vh = (rh > 0.f) ? vh : 0.f;
                dg = pk(vl, vh);
            }
            *(u64*)&recW[(20 + g) * RSC + cj] = dg;
            const float* r = &P[52 + 12 * g];
            float4 wa = *(const float4*)r;
            float4 wb = *(const float4*)(r + 4);
            float2 wc = *(const float2*)(r + 8);
            dh[0] = ffma2(dup(wa.x), dg, dh[0]);
            dh[1] = ffma2(dup(wa.y), dg, dh[1]);
            dh[2] = ffma2(dup(wa.z), dg, dh[2]);
            dh[3] = ffma2(dup(wa.w), dg, dh[3]);
            dh[4] = ffma2(dup(wb.x), dg, dh[4]);
            dh[5] = ffma2(dup(wb.y), dg, dh[5]);
            dh[6] = ffma2(dup(wb.z), dg, dh[6]);
            dh[7] = ffma2(dup(wb.w), dg, dh[7]);
            dh[8] = ffma2(dup(wc.x), dg, dh[8]);
            dh[9] = ffma2(dup(wc.y), dg, dh[9]);
        }
#pragma unroll
        for (int h = 0; h < 10; h++) {
            float vl, vh, rl, rh; upk(dh[h], vl, vh); upk(h1p[h], rl, rh);
            vl = (rl > 0.f) ? vl : 0.f;
            vh = (rh > 0.f) ? vh : 0.f;
            *(u64*)&recW[h * RSC + cj] = pk(vl, vh);
        }
        __syncwarp();

        // ---- unified minipass: 8 LDS.64 + 8 FFMA2 per iter ----
#pragma unroll 8
        for (int i = 0; i < CHUNK / 2; i++) {
            u64 a0 = t1a0[i], a1 = t1a1[i], b0 = t1b0[i], b1 = t1b1[i];
            m0a = ffma2(a0, b0, m0a);
            m1a = ffma2(a0, b1, m1a);
            m2a = ffma2(a1, b0, m2a);
            m3a = ffma2(a1, b1, m3a);
            u64 e0 = t2a0[i], e1 = t2a1[i], f0 = t2b0[i], f1 = t2b1[i];
            m4a = ffma2(e0, f0, m4a);
            m5a = ffma2(e0, f1, m5a);
            m6a = ffma2(e1, f0, m6a);
            m7a = ffma2(e1, f1, m7a);
        }
        t2b0 += t2adv;
        t2b1 += t2adv;
        __syncwarp();   // before next chunk overwrites rec rows
    }

    // ---- finalize grads, sumsq ----
    float ssq = 0.f;
    float* gout = wout + 193;
    {
        float lo, hi, v;
#define EMIT(ACC, IDX) do { \
        if ((IDX) >= 0) { upk(ACC, lo, hi); v = lo + hi; \
            gout[(IDX)] = v; ssq = fmaf(v, v, ssq); } } while (0)
        EMIT(m0a, id[0]); EMIT(m1a, id[1]); EMIT(m2a, id[2]); EMIT(m3a, id[3]);
        EMIT(m4a, id[4]); EMIT(m5a, id[5]); EMIT(m6a, id[6]); EMIT(m7a, id[7]);
#undef EMIT
    }

    float lossacc = l0acc + l1acc;
    lossacc += __shfl_xor_sync(0xffffffffu, lossacc, 16);
    lossacc += __shfl_xor_sync(0xffffffffu, lossacc, 8);
    lossacc += __shfl_xor_sync(0xffffffffu, lossacc, 4);
    lossacc += __shfl_xor_sync(0xffffffffu, lossacc, 2);
    lossacc += __shfl_xor_sync(0xffffffffu, lossacc, 1);
    const float loss_b = lossacc * invN;

    ssq += __shfl_xor_sync(0xffffffffu, ssq, 16);
    ssq += __shfl_xor_sync(0xffffffffu, ssq, 8);
    ssq += __shfl_xor_sync(0xffffffffu, ssq, 4);
    ssq += __shfl_xor_sync(0xffffffffu, ssq, 2);
    ssq += __shfl_xor_sync(0xffffffffu, ssq, 1);

    if (lane == 0) {
        atomicAdd(&g_sumsq, ssq);
        wout[386] = loss_b;
        wout[387] = clip1e4(fv[b] - loss_b);
    }
}

// Apply global grad-norm clip coefficient to the grad columns [193, 386).
__global__ void k_scale(float* __restrict__ out) {
    const float coef = fminf(1.f, 10.f / (sqrtf(g_sumsq) + 1e-6f));
    const int b = blockIdx.x;
    const int k = threadIdx.x;
    if (k < 193) {
        size_t idx = (size_t)b * 388 + 193 + k;
        out[idx] *= coef;
    }
}

extern "C" void kernel_launch(void* const* d_in, const int* in_sizes, int n_in,
                              void* d_out, int out_size)
{
    const float* W1 = (const float*)d_in[0];
    const float* b1 = (const float*)d_in[1];
    const float* W2 = (const float*)d_in[2];
    const float* b2 = (const float*)d_in[3];
    const float* W3 = (const float*)d_in[4];
    const float* b3 = (const float*)d_in[5];
    const float* G1 = (const float*)d_in[6];
    const float* G2 = (const float*)d_in[7];
    const float* G3 = (const float*)d_in[8];
    const float* G4 = (const float*)d_in[9];
    const float* G5 = (const float*)d_in[10];
    const float* G6 = (const float*)d_in[11];
    const float* dx = (const float*)d_in[12];
    const float* fv = (const float*)d_in[13];
    const int*   dy = (const int*)d_in[14];
    const int*   ss = (const int*)d_in[15];
    float* out = (float*)d_out;

    const int B = in_sizes[13];   // func_val is [B]

    static int carveout_set = 0;
    if (!carveout_set) {
        cudaFuncSetAttribute(k_main,
                             cudaFuncAttributePreferredSharedMemoryCarveout,
                             cudaSharedmemCarveoutMaxShared);
        carveout_set = 1;
    }

    // g_sumsq is 0 on entry: static init on first call, k_zero (below) after.
    k_main<<<B / WPB, BDIM>>>(W1, b1, W2, b2, W3, b3,
                              G1, G2, G3, G4, G5, G6,
                              dx, fv, dy, ss, out);
    k_scale<<<B, 224>>>(out);
    k_zero<<<1, 1>>>();          // reset for the next (graph-replayed) call
}

// round 7
// speedup vs baseline: 1.8979x; 1.2729x over previous
#include <cuda_runtime.h>

#define BDIM 64
#define WPB 2             // warps (MLPs) per block
#define RSC 68            // rec row stride; mult of 4 (16B align), ==4 mod 32
#define NROWS 51
#define RECW (NROWS * RSC)
#define PSTRIDE 264
#define NS 150

typedef unsigned long long u64;

__constant__ float c_lr[6] = {0.001f, 0.01f, 0.05f, 0.1f, 0.5f, 1.0f};
__device__ float g_sumsq = 0.f;   // zeroed by k_zero at END of each call

__device__ __forceinline__ float clip1e4(float v) {
    return fminf(fmaxf(v, -10000.f), 10000.f);
}
__device__ __forceinline__ u64 pk(float lo, float hi) {
    u64 r; asm("mov.b64 %0, {%1,%2};" : "=l"(r) : "f"(lo), "f"(hi)); return r;
}
__device__ __forceinline__ u64 dup(float v) {
    u64 r; asm("mov.b64 %0, {%1,%1};" : "=l"(r) : "f"(v)); return r;
}
__device__ __forceinline__ void upk(u64 v, float& lo, float& hi) {
    asm("mov.b64 {%0,%1}, %2;" : "=f"(lo), "=f"(hi) : "l"(v));
}
__device__ __forceinline__ u64 ffma2(u64 a, u64 b, u64 c) {
    u64 d; asm("fma.rn.f32x2 %0, %1, %2, %3;" : "=l"(d) : "l"(a), "l"(b), "l"(c));
    return d;
}
__device__ __forceinline__ u64 fmul2(u64 a, u64 b) {
    u64 d; asm("mul.rn.f32x2 %0, %1, %2;" : "=l"(d) : "l"(a), "l"(b)); return d;
}
__device__ __forceinline__ u64 add2(u64 a, u64 b) {
    u64 d; asm("add.rn.f32x2 %0, %1, %2;" : "=l"(d) : "l"(a), "l"(b)); return d;
}

__global__ void k_zero() { g_sumsq = 0.f; }

// rec row map (per warp):
//  0..9  dhm    10..19 h1    20..29 dg    30..39 h2
//  43 x0  48 x1  44 x2  49 x3     45 d0  50 d1  47 d2
// (placement chosen so each minipass load instruction's distinct rows have
//  distinct (row mod 8) bank groups at RSC=68)
__global__ void __launch_bounds__(BDIM, 6) k_main(
    const float* __restrict__ W1, const float* __restrict__ b1,
    const float* __restrict__ W2, const float* __restrict__ b2,
    const float* __restrict__ W3, const float* __restrict__ b3,
    const float* __restrict__ G1, const float* __restrict__ G2,
    const float* __restrict__ G3, const float* __restrict__ G4,
    const float* __restrict__ G5, const float* __restrict__ G6,
    const float* __restrict__ dx, const float* __restrict__ fv,
    const int* __restrict__ dy, const int* __restrict__ ss,
    float* __restrict__ out)
{
    __shared__ __align__(16) float ps[WPB * PSTRIDE];
    __shared__ __align__(16) float rec[WPB * RECW];

    const int tid  = threadIdx.x;
    const int lane = tid & 31;
    const int warp = tid >> 5;
    const int b    = blockIdx.x * WPB + warp;

    float* P    = ps  + warp * PSTRIDE;
    float* recW = rec + warp * RECW;
    // P layout: 0:W1[10x4] 40:b1[10] 52:W2 rows stride 12 (10 rows)
    // 172:b2[10] 184:W3 rows stride 12 (3 rows) 220:b3[3] 224:W3^T stride 4

    const float lr = c_lr[ss[b]];
    float* wout = out + (size_t)b * 388;

    for (int k = lane; k < PSTRIDE; k += 32) P[k] = 0.f;
    __syncwarp();
    for (int k = lane; k < 40; k += 32) {
        float p = fmaf(-lr, G1[b * 40 + k], W1[b * 40 + k]);
        P[k] = p; wout[k] = clip1e4(p);
    }
    for (int k = lane; k < 10; k += 32) {
        float p = fmaf(-lr, G2[b * 10 + k], b1[b * 10 + k]);
        P[40 + k] = p; wout[40 + k] = clip1e4(p);
    }
    for (int k = lane; k < 100; k += 32) {
        float p = fmaf(-lr, G3[b * 100 + k], W2[b * 100 + k]);
        int r = k / 10, c = k - r * 10;
        P[52 + 12 * r + c] = p; wout[50 + k] = clip1e4(p);
    }
    for (int k = lane; k < 10; k += 32) {
        float p = fmaf(-lr, G4[b * 10 + k], b2[b * 10 + k]);
        P[172 + k] = p; wout[150 + k] = clip1e4(p);
    }
    for (int k = lane; k < 30; k += 32) {
        float p = fmaf(-lr, G5[b * 30 + k], W3[b * 30 + k]);
        int r = k / 10, c = k - r * 10;
        P[184 + 12 * r + c] = p;
        P[224 + 4 * c + r]  = p;                 // W3^T (rows stride 4)
        wout[160 + k] = clip1e4(p);
    }
    for (int k = lane; k < 3; k += 32) {
        float p = fmaf(-lr, G6[b * 3 + k], b3[b * 3 + k]);
        P[220 + k] = p; wout[190 + k] = clip1e4(p);
    }
    __syncwarp();

    // ---- minipass offsets (floats from recW), bank-planned ----
    int oa0, oa1, ob0, ob1;                 // tile-set 1: gW2 5x5 pair tiles
    {
        int q = (lane < 25) ? lane / 5 : 0;
        int r = (lane < 25) ? lane % 5 : 0;
        oa0 = (20 + q) * RSC; oa1 = (25 + q) * RSC;   // dg rows (A)
        ob0 = (10 + r) * RSC; ob1 = (15 + r) * RSC;   // h1 rows (B)
    }
    int oe0, oe1, of0, of1;                 // tile-set 2: gW1 / gW3
    if (lane < 10) {
        int a = lane >> 1, bq = lane & 1;
        oe0 = a * RSC; oe1 = (a + 5) * RSC;                  // dhm rows
        of0 = (bq ? 44 : 43) * RSC; of1 = (bq ? 49 : 48) * RSC; // x rows
    } else if (lane < 20) {
        int l = lane - 10, p = l / 5, qh = l % 5;
        oe0 = (p ? 47 : 45) * RSC; oe1 = 50 * RSC;           // d rows
        of0 = (30 + qh) * RSC; of1 = (35 + qh) * RSC;        // h2 rows
    } else {
        oe0 = 0; oe1 = 5 * RSC; of0 = 43 * RSC; of1 = 48 * RSC; // dummies
    }

    u64 m0 = 0ull, m1 = 0ull, m2 = 0ull, m3 = 0ull;
    u64 m4 = 0ull, m5 = 0ull, m6 = 0ull, m7 = 0ull;
    u64 sa0 = 0ull, sa1 = 0ull, se0 = 0ull, se1 = 0ull;   // bias sums

    float l0acc = 0.f, l1acc = 0.f;
    const float invN = 1.f / 150.f;
    const int cj = 2 * lane;

#pragma unroll 1
    for (int c = 0; c < 3; c++) {
        const int s0 = 64 * c + cj;
        const bool m = (s0 < NS);           // NS even, s0 even -> one mask
        float4 xa = make_float4(0.f, 0.f, 0.f, 0.f);
        float4 xb = xa;
        int2 y01 = make_int2(0, 0);
        if (m) {
            xa = ((const float4*)dx)[s0];
            xb = ((const float4*)dx)[s0 + 1];
            y01 = *(const int2*)&dy[s0];
        }
        const u64 x0p = pk(xa.x, xb.x);
        const u64 x1p = pk(xa.y, xb.y);
        const u64 x2p = pk(xa.z, xb.z);
        const u64 x3p = pk(xa.w, xb.w);
        *(u64*)&recW[43 * RSC + cj] = x0p;
        *(u64*)&recW[48 * RSC + cj] = x1p;
        *(u64*)&recW[44 * RSC + cj] = x2p;
        *(u64*)&recW[49 * RSC + cj] = x3p;

        // layer 1
        u64 h1p[10];
#pragma unroll
        for (int h = 0; h < 10; h++) {
            float4 w = *(const float4*)&P[4 * h];
            u64 a = fmul2(dup(w.x), x0p);
            a = ffma2(dup(w.y), x1p, a);
            a = ffma2(dup(w.z), x2p, a);
            a = ffma2(dup(w.w), x3p, a);
            float lo, hi; upk(a, lo, hi);
            float bb = P[40 + h];
            lo = fmaxf(lo + bb, 0.f);
            hi = fmaxf(hi + bb, 0.f);
            u64 v = pk(lo, hi);
            h1p[h] = v;
            *(u64*)&recW[(10 + h) * RSC + cj] = v;
        }
        // layer 2
        u64 h2p[10];
#pragma unroll
        for (int g = 0; g < 10; g++) {
            const float* r = &P[52 + 12 * g];
            float4 wa = *(const float4*)r;
            float4 wb = *(const float4*)(r + 4);
            float2 wc = *(const float2*)(r + 8);
            u64 a = fmul2(dup(wa.x), h1p[0]);
            a = ffma2(dup(wa.y), h1p[1], a);
            a = ffma2(dup(wa.z), h1p[2], a);
            a = ffma2(dup(wa.w), h1p[3], a);
            a = ffma2(dup(wb.x), h1p[4], a);
            a = ffma2(dup(wb.y), h1p[5], a);
            a = ffma2(dup(wb.z), h1p[6], a);
            a = ffma2(dup(wb.w), h1p[7], a);
            a = ffma2(dup(wc.x), h1p[8], a);
            a = ffma2(dup(wc.y), h1p[9], a);
            float lo, hi; upk(a, lo, hi);
            float bb = P[172 + g];
            lo = fmaxf(lo + bb, 0.f);
            hi = fmaxf(hi + bb, 0.f);
            u64 v = pk(lo, hi);
            h2p[g] = v;
            *(u64*)&recW[(30 + g) * RSC + cj] = v;
        }
        // layer 3 logits
        float lgl[3], lgh[3];
#pragma unroll
        for (int o = 0; o < 3; o++) {
            const float* r = &P[184 + 12 * o];
            float4 wa = *(const float4*)r;
            float4 wb = *(const float4*)(r + 4);
            float2 wc = *(const float2*)(r + 8);
            u64 a = fmul2(dup(wa.x), h2p[0]);
            a = ffma2(dup(wa.y), h2p[1], a);
            a = ffma2(dup(wa.z), h2p[2], a);
            a = ffma2(dup(wa.w), h2p[3], a);
            a = ffma2(dup(wb.x), h2p[4], a);
            a = ffma2(dup(wb.y), h2p[5], a);
            a = ffma2(dup(wb.z), h2p[6], a);
            a = ffma2(dup(wb.w), h2p[7], a);
            a = ffma2(dup(wc.x), h2p[8], a);
            a = ffma2(dup(wc.y), h2p[9], a);
            float lo, hi; upk(a, lo, hi);
            float bb = P[220 + o];
            lgl[o] = lo + bb;
            lgh[o] = hi + bb;
        }
        // softmax + CE (per half; one shared mask)
        const float km = m ? invN : 0.f;
        float d00, d01, d02, d10, d11, d12;
        {
            float mm = fmaxf(lgl[0], fmaxf(lgl[1], lgl[2]));
            float e0 = __expf(lgl[0] - mm), e1 = __expf(lgl[1] - mm), e2 = __expf(lgl[2] - mm);
            float sm = e0 + e1 + e2, iv = __fdividef(1.f, sm);
            int y = y01.x;
            float ly = (y == 0) ? lgl[0] : ((y == 1) ? lgl[1] : lgl[2]);
            l0acc += m ? ((mm - ly) + __logf(sm)) : 0.f;
            d00 = (e0 * iv - (y == 0 ? 1.f : 0.f)) * km;
            d01 = (e1 * iv - (y == 1 ? 1.f : 0.f)) * km;
            d02 = (e2 * iv - (y == 2 ? 1.f : 0.f)) * km;
        }
        {
            float mm = fmaxf(lgh[0], fmaxf(lgh[1], lgh[2]));
            float e0 = __expf(lgh[0] - mm), e1 = __expf(lgh[1] - mm), e2 = __expf(lgh[2] - mm);
            float sm = e0 + e1 + e2, iv = __fdividef(1.f, sm);
            int y = y01.y;
            float ly = (y == 0) ? lgh[0] : ((y == 1) ? lgh[1] : lgh[2]);
            l1acc += m ? ((mm - ly) + __logf(sm)) : 0.f;
            d10 = (e0 * iv - (y == 0 ? 1.f : 0.f)) * km;
            d11 = (e1 * iv - (y == 1 ? 1.f : 0.f)) * km;
            d12 = (e2 * iv - (y == 2 ? 1.f : 0.f)) * km;
        }
        u64 d0p = pk(d00, d10), d1p = pk(d01, d11), d2p = pk(d02, d12);
        *(u64*)&recW[45 * RSC + cj] = d0p;
        *(u64*)&recW[50 * RSC + cj] = d1p;
        *(u64*)&recW[47 * RSC + cj] = d2p;

        // backward: dg rows, dh1 accumulation
        u64 dh[10];
#pragma unroll
        for (int h = 0; h < 10; h++) dh[h] = 0ull;
#pragma unroll
        for (int g = 0; g < 10; g++) {
            float4 wt = *(const float4*)&P[224 + 4 * g];
            u64 dg = fmul2(dup(wt.x), d0p);
            dg = ffma2(dup(wt.y), d1p, dg);
            dg = ffma2(dup(wt.z), d2p, dg);
            {
                float vl, vh, rl, rh; upk(dg, vl, vh); upk(h2p[g], rl, rh);
                vl = (rl > 0.f) ? vl : 0.f;
                vh = (rh > 0.f) ? vh : 0.f;
                dg = pk(vl, vh);
            }
            *(u64*)&recW[(20 + g) * RSC + cj] = dg;
            const float* r = &P[52 + 12 * g];
            float4 wa = *(const float4*)r;
            float4 wb = *(const float4*)(r + 4);
            float2 wc = *(const float2*)(r + 8);
            dh[0] = ffma2(dup(wa.x), dg, dh[0]);
            dh[1] = ffma2(dup(wa.y), dg, dh[1]);
            dh[2] = ffma2(dup(wa.z), dg, dh[2]);
            dh[3] = ffma2(dup(wa.w), dg, dh[3]);
            dh[4] = ffma2(dup(wb.x), dg, dh[4]);
            dh[5] = ffma2(dup(wb.y), dg, dh[5]);
            dh[6] = ffma2(dup(wb.z), dg, dh[6]);
            dh[7] = ffma2(dup(wb.w), dg, dh[7]);
            dh[8] = ffma2(dup(wc.x), dg, dh[8]);
            dh[9] = ffma2(dup(wc.y), dg, dh[9]);
        }
#pragma unroll
        for (int h = 0; h < 10; h++) {
            float vl, vh, rl, rh; upk(dh[h], vl, vh); upk(h1p[h], rl, rh);
            vl = (rl > 0.f) ? vl : 0.f;
            vh = (rh > 0.f) ? vh : 0.f;
            *(u64*)&recW[h * RSC + cj] = pk(vl, vh);
        }
        __syncwarp();

        // ---- minipass: LDS.128 tiles + free bias sums ----
        const int nsteps = (c == 2) ? 6 : 16;   // chunk3: 22 valid samples
#pragma unroll 2
        for (int i = 0; i < nsteps; i++) {
            ulonglong2 a0 = *(const ulonglong2*)&recW[oa0 + 4 * i];
            ulonglong2 a1 = *(const ulonglong2*)&recW[oa1 + 4 * i];
            ulonglong2 b0 = *(const ulonglong2*)&recW[ob0 + 4 * i];
            ulonglong2 b1 = *(const ulonglong2*)&recW[ob1 + 4 * i];
            m0 = ffma2(a0.x, b0.x, m0); m0 = ffma2(a0.y, b0.y, m0);
            m1 = ffma2(a0.x, b1.x, m1); m1 = ffma2(a0.y, b1.y, m1);
            m2 = ffma2(a1.x, b0.x, m2); m2 = ffma2(a1.y, b0.y, m2);
            m3 = ffma2(a1.x, b1.x, m3); m3 = ffma2(a1.y, b1.y, m3);
            sa0 = add2(sa0, add2(a0.x, a0.y));
            sa1 = add2(sa1, add2(a1.x, a1.y));
            ulonglong2 e0 = *(const ulonglong2*)&recW[oe0 + 4 * i];
            ulonglong2 e1 = *(const ulonglong2*)&recW[oe1 + 4 * i];
            ulonglong2 f0 = *(const ulonglong2*)&recW[of0 + 4 * i];
            ulonglong2 f1 = *(const ulonglong2*)&recW[of1 + 4 * i];
            m4 = ffma2(e0.x, f0.x, m4); m4 = ffma2(e0.y, f0.y, m4);
            m5 = ffma2(e0.x, f1.x, m5); m5 = ffma2(e0.y, f1.y, m5);
            m6 = ffma2(e1.x, f0.x, m6); m6 = ffma2(e1.y, f0.y, m6);
            m7 = ffma2(e1.x, f1.x, m7); m7 = ffma2(e1.y, f1.y, m7);
            se0 = add2(se0, add2(e0.x, e0.y));
            se1 = add2(se1, add2(e1.x, e1.y));
        }
        __syncwarp();   // before next chunk overwrites rec rows
    }

    // ---- finalize grads, sumsq ----
    float ssq = 0.f;
    float* gout = wout + 193;
    float lo, hi, v;
#define EMIT(ACC, IDX) do { upk(ACC, lo, hi); v = lo + hi; \
        gout[(IDX)] = v; ssq = fmaf(v, v, ssq); } while (0)
    if (lane < 25) {
        int q = lane / 5, r = lane % 5;
        EMIT(m0, 50 + 10 * q + r);
        EMIT(m1, 55 + 10 * q + r);
        EMIT(m2, 100 + 10 * q + r);
        EMIT(m3, 105 + 10 * q + r);
        if (r == 0) { EMIT(sa0, 150 + q); EMIT(sa1, 155 + q); }
    }
    if (lane < 10) {
        int a = lane >> 1, bq = lane & 1;
        int bs = 4 * a + 2 * bq;
        EMIT(m4, bs); EMIT(m5, bs + 1); EMIT(m6, bs + 20); EMIT(m7, bs + 21);
        if (bq == 0) { EMIT(se0, 40 + a); EMIT(se1, 45 + a); }
    } else if (lane < 20) {
        int l = lane - 10, p = l / 5, qh = l % 5;
        if (p == 0) {
            EMIT(m4, 160 + qh); EMIT(m5, 165 + qh);
            EMIT(m6, 170 + qh); EMIT(m7, 175 + qh);
            if (qh == 0) { EMIT(se0, 190); EMIT(se1, 191); }
        } else {
            EMIT(m4, 180 + qh); EMIT(m5, 185 + qh);
            if (qh == 0) { EMIT(se0, 192); }
        }
    }
#undef EMIT

    float lossacc = l0acc + l1acc;
    lossacc += __shfl_xor_sync(0xffffffffu, lossacc, 16);
    lossacc += __shfl_xor_sync(0xffffffffu, lossacc, 8);
    lossacc += __shfl_xor_sync(0xffffffffu, lossacc, 4);
    lossacc += __shfl_xor_sync(0xffffffffu, lossacc, 2);
    lossacc += __shfl_xor_sync(0xffffffffu, lossacc, 1);
    const float loss_b = lossacc * invN;

    ssq += __shfl_xor_sync(0xffffffffu, ssq, 16);
    ssq += __shfl_xor_sync(0xffffffffu, ssq, 8);
    ssq += __shfl_xor_sync(0xffffffffu, ssq, 4);
    ssq += __shfl_xor_sync(0xffffffffu, ssq, 2);
    ssq += __shfl_xor_sync(0xffffffffu, ssq, 1);

    if (lane == 0) {
        atomicAdd(&g_sumsq, ssq);
        wout[386] = loss_b;
        wout[387] = clip1e4(fv[b] - loss_b);
    }
}

// Apply global grad-norm clip coefficient to the grad columns [193, 386).
__global__ void k_scale(float* __restrict__ out) {
    const float coef = fminf(1.f, 10.f / (sqrtf(g_sumsq) + 1e-6f));
    const int b = blockIdx.x;
    const int k = threadIdx.x;
    if (k < 193) {
        size_t idx = (size_t)b * 388 + 193 + k;
        out[idx] *= coef;
    }
}

extern "C" void kernel_launch(void* const* d_in, const int* in_sizes, int n_in,
                              void* d_out, int out_size)
{
    const float* W1 = (const float*)d_in[0];
    const float* b1 = (const float*)d_in[1];
    const float* W2 = (const float*)d_in[2];
    const float* b2 = (const float*)d_in[3];
    const float* W3 = (const float*)d_in[4];
    const float* b3 = (const float*)d_in[5];
    const float* G1 = (const float*)d_in[6];
    const float* G2 = (const float*)d_in[7];
    const float* G3 = (const float*)d_in[8];
    const float* G4 = (const float*)d_in[9];
    const float* G5 = (const float*)d_in[10];
    const float* G6 = (const float*)d_in[11];
    const float* dx = (const float*)d_in[12];
    const float* fv = (const float*)d_in[13];
    const int*   dy = (const int*)d_in[14];
    const int*   ss = (const int*)d_in[15];
    float* out = (float*)d_out;

    const int B = in_sizes[13];   // func_val is [B]

    static int carveout_set = 0;
    if (!carveout_set) {
        cudaFuncSetAttribute(k_main,
                             cudaFuncAttributePreferredSharedMemoryCarveout,
                             cudaSharedmemCarveoutMaxShared);
        carveout_set = 1;
    }

    // g_sumsq is 0 on entry: static init on first call, k_zero (below) after.
    k_main<<<B / WPB, BDIM>>>(W1, b1, W2, b2, W3, b3,
                              G1, G2, G3, G4, G5, G6,
                              dx, fv, dy, ss, out);
    k_scale<<<B, 224>>>(out);
    k_zero<<<1, 1>>>();          // reset for the next (graph-replayed) call
}